// round 8
// baseline (speedup 1.0000x reference)
#include <cuda_runtime.h>
#include <math.h>

#define B 32
#define T 512
#define U 1024
#define E 1024
#define DIN 256
#define G4 4096        // 4*U
#define NSPL_IND 10    // independent z chunks (2 inputs + 8 h), k=128 each
#define NSPL_CTX 16    // context z chunks, k=64 each
#define NSPL (NSPL_IND + NSPL_CTX)
#define NT 512

// ---------------- scratch (device globals: no allocations allowed) ----------
__device__ float g_qpart[16 * B * U];
__device__ float g_logits[B * T];
__device__ float g_ctxpart[16 * B * E];
__device__ float g_zpart[NSPL * B * G4];
__device__ unsigned int g_count = 0;     // barrier arrive counter (self-resets)
__device__ unsigned int g_gen = 0;       // barrier generation (monotonic)
__device__ unsigned int g_tick[4] = {0, 0, 0, 0};  // work-steal tickets per phase

// ---------------- helpers ----------------------------------------------------
__device__ __forceinline__ unsigned long long pack2(float a, float b) {
    unsigned long long r;
    asm("mov.b64 %0, {%1, %2};" : "=l"(r) : "r"(__float_as_uint(a)), "r"(__float_as_uint(b)));
    return r;
}
__device__ __forceinline__ void unpack2(unsigned long long v, float& a, float& b) {
    unsigned int lo, hi;
    asm("mov.b64 {%0, %1}, %2;" : "=r"(lo), "=r"(hi) : "l"(v));
    a = __uint_as_float(lo); b = __uint_as_float(hi);
}
__device__ __forceinline__ unsigned long long fma2(unsigned long long x,
                                                   unsigned long long y,
                                                   unsigned long long a) {
    unsigned long long d;
    asm("fma.rn.f32x2 %0, %1, %2, %3;" : "=l"(d) : "l"(x), "l"(y), "l"(a));
    return d;
}
__device__ __forceinline__ float tanh_hw(float x) {
    float y;
    asm("tanh.approx.f32 %0, %1;" : "=f"(y) : "f"(x));
    return y;
}
__device__ __forceinline__ float sigmoid_acc(float x) {
    return 1.0f / (1.0f + expf(-x));
}

// Grid-wide barrier (uses gridDim.x; replay-safe: count self-resets, gen grows)
__device__ __forceinline__ void grid_barrier() {
    __syncthreads();
    if (threadIdx.x == 0) {
        __threadfence();
        unsigned int gen = atomicAdd(&g_gen, 0u);
        unsigned int arrived = atomicAdd(&g_count, 1u) + 1u;
        if (arrived == gridDim.x) {
            g_count = 0;
            __threadfence();
            atomicAdd(&g_gen, 1u);
        } else {
            while (atomicAdd(&g_gen, 0u) == gen) { __nanosleep(32); }
        }
        __threadfence();
    }
    __syncthreads();
}

// ---------------- the whole cell: 5 phases, work-stealing ---------------------
__global__ void __launch_bounds__(NT, 3) mono_cell(
    const float* __restrict__ inputs, const float* __restrict__ h,
    const float* __restrict__ c, const float* __restrict__ se,
    const float* __restrict__ es, const float* __restrict__ Wa,
    const float* __restrict__ Wa_b, const float* __restrict__ va_w,
    const float* __restrict__ va_b, const float* __restrict__ Wk,
    const float* __restrict__ Wr, const float* __restrict__ bias,
    float* __restrict__ out)
{
    __shared__ __align__(16) float pool[128 * 36];   // 18.4KB, reused per phase
    __shared__ unsigned int s_tile;
    const int tid = threadIdx.x;

    // ===== PA (tick 0): 224 tiles = 64 query-partial + 160 independent-z ======
    for (;;) {
        __syncthreads();
        if (tid == 0) s_tile = atomicAdd(&g_tick[0], 1u);
        __syncthreads();
        const unsigned int tile = s_tile;
        if (tile >= 224u) break;

        if (tile < 64u) {
            // query partial: h[32,1024] @ Wa, k-split 64, u-tile 256
            const int ut = tile >> 4, kb = tile & 15;
            const int k0 = kb * 64;
            const int u = ut * 256 + (tid & 255);
            const int bh = tid >> 8;

            for (int idx = tid; idx < 32 * 64; idx += NT) {
                int b = idx >> 6, k = idx & 63;
                pool[k * 36 + b] = h[b * U + k0 + k];
            }
            __syncthreads();

            unsigned long long acc[8];
#pragma unroll
            for (int p = 0; p < 8; p++) acc[p] = 0ull;
            const float* wcol = Wa + (size_t)k0 * U + u;
#pragma unroll 8
            for (int k = 0; k < 64; k++) {
                float w = wcol[(size_t)k * U];
                unsigned long long ww = pack2(w, w);
                const unsigned long long* xp =
                    reinterpret_cast<const unsigned long long*>(&pool[k * 36]) + bh * 8;
#pragma unroll
                for (int p = 0; p < 8; p++) acc[p] = fma2(xp[p], ww, acc[p]);
            }
            float* outp = g_qpart + (size_t)kb * (B * U);
#pragma unroll
            for (int p = 0; p < 8; p++) {
                float a, b2; unpack2(acc[p], a, b2);
                outp[(bh * 16 + 2 * p) * U + u] = a;
                outp[(bh * 16 + 2 * p + 1) * U + u] = b2;
            }
        } else {
            // independent z: kb 0..1 inputs (k=128), 2..9 h (k=128); j-tile 256
            const unsigned int zi = tile - 64u;
            const int kb = zi >> 4, jt = zi & 15;
            const int j = jt * 256 + (tid & 255);
            const int bh = tid >> 8;

            const float* xsrc; int x_ld, xk0;
            const float* W;    int wk0;
            if (kb < 2) { xsrc = inputs; x_ld = DIN; xk0 = kb * 128;       W = Wk; wk0 = kb * 128; }
            else        { xsrc = h;      x_ld = U;   xk0 = (kb - 2) * 128; W = Wr; wk0 = (kb - 2) * 128; }

            for (int idx = tid; idx < 32 * 128; idx += NT) {
                int b = idx >> 7, kk = idx & 127;
                pool[kk * 36 + b] = xsrc[(size_t)b * x_ld + xk0 + kk];
            }
            __syncthreads();

            unsigned long long acc[8];
#pragma unroll
            for (int p = 0; p < 8; p++) acc[p] = 0ull;
            const float* wcol = W + (size_t)wk0 * G4 + j;
#pragma unroll 8
            for (int kk = 0; kk < 128; kk++) {
                float w = wcol[(size_t)kk * G4];
                unsigned long long ww = pack2(w, w);
                const unsigned long long* xp =
                    reinterpret_cast<const unsigned long long*>(&pool[kk * 36]) + bh * 8;
#pragma unroll
                for (int p = 0; p < 8; p++) acc[p] = fma2(xp[p], ww, acc[p]);
            }
            float* outp = g_zpart + (size_t)kb * (B * G4);
#pragma unroll
            for (int p = 0; p < 8; p++) {
                float a, b2; unpack2(acc[p], a, b2);
                outp[(size_t)(bh * 16 + 2 * p) * G4 + j] = a;
                outp[(size_t)(bh * 16 + 2 * p + 1) * G4 + j] = b2;
            }
        }
    }
    grid_barrier();

    // ===== PB (tick 1): scores, 512 tiles = (b, 32-row slice) =================
    if (blockIdx.x == 0 && tid == 0) g_tick[0] = 0;
    {
        int cur_b = -1;
        const float vb = va_b[0];
        const int lane = tid & 31;
        for (;;) {
            __syncthreads();
            if (tid == 0) s_tile = atomicAdd(&g_tick[1], 1u);
            __syncthreads();
            const unsigned int tile = s_tile;
            if (tile >= 512u) break;
            const int b = tile >> 4, sl = tile & 15;

            if (b != cur_b) {
                // prologue: reduce query[b] + load va into smem
                for (int col = tid; col < U; col += NT) {
                    float s = Wa_b[col];
#pragma unroll
                    for (int kb = 0; kb < 16; kb++)
                        s += g_qpart[kb * (B * U) + b * U + col];
                    pool[col] = s;
                }
                for (int i4 = tid; i4 < 256; i4 += NT)
                    reinterpret_cast<float4*>(pool + 1024)[i4] =
                        reinterpret_cast<const float4*>(va_w)[i4];
                __syncthreads();
                cur_b = b;
            }

            const float4* qs = reinterpret_cast<const float4*>(pool);
            const float4* vs = reinterpret_cast<const float4*>(pool + 1024);
#pragma unroll
            for (int rr = 0; rr < 2; rr++) {
                const int r = sl * 32 + (tid >> 5) * 2 + rr;
                const float4* erow = reinterpret_cast<const float4*>(es)
                                   + (size_t)(b * T + r) * 256;
                float s = 0.f;
#pragma unroll
                for (int hh = 0; hh < 2; hh++) {
                    float4 e0 = erow[lane + (hh * 4 + 0) * 32];
                    float4 e1 = erow[lane + (hh * 4 + 1) * 32];
                    float4 e2 = erow[lane + (hh * 4 + 2) * 32];
                    float4 e3 = erow[lane + (hh * 4 + 3) * 32];
#pragma unroll
                    for (int i = 0; i < 4; i++) {
                        float4 ee = (i == 0) ? e0 : (i == 1) ? e1 : (i == 2) ? e2 : e3;
                        int u4 = lane + (hh * 4 + i) * 32;
                        float4 q4 = qs[u4];
                        float4 v4 = vs[u4];
                        s += tanh_hw(q4.x + ee.x) * v4.x;
                        s += tanh_hw(q4.y + ee.y) * v4.y;
                        s += tanh_hw(q4.z + ee.z) * v4.z;
                        s += tanh_hw(q4.w + ee.w) * v4.w;
                    }
                }
#pragma unroll
                for (int o = 16; o; o >>= 1) s += __shfl_xor_sync(0xffffffffu, s, o);
                if (lane == 0) g_logits[b * T + r] = s + vb;
            }
        }
    }
    grid_barrier();

    // ===== PC (tick 2): softmax (cached per b) + context partials =============
    // 256 tiles = b(32) x half(2) x tc(4); partial pp = tc*4+sub over 32 t.
    if (blockIdx.x == 0 && tid == 0) g_tick[1] = 0;
    {
        int cur_b = -1;
        float inv = 0.f;
        float* ps = pool;            // [0,512)
        float* red = pool + 512;     // [512,530)
        const int lane = tid & 31, wid = tid >> 5;
        for (;;) {
            __syncthreads();
            if (tid == 0) s_tile = atomicAdd(&g_tick[2], 1u);
            __syncthreads();
            const unsigned int tile = s_tile;
            if (tile >= 256u) break;
            const int b = tile >> 3, half = (tile >> 2) & 1, tc = tile & 3;

            if (b != cur_b) {
                float l = g_logits[b * T + tid];
                float m = l;
#pragma unroll
                for (int o = 16; o; o >>= 1) m = fmaxf(m, __shfl_xor_sync(0xffffffffu, m, o));
                if (lane == 0) red[wid] = m;
                __syncthreads();
                if (tid < 32) {
                    float v = red[tid & 15];
#pragma unroll
                    for (int o = 8; o; o >>= 1) v = fmaxf(v, __shfl_xor_sync(0xffffffffu, v, o));
                    if (tid == 0) red[16] = v;
                }
                __syncthreads();
                float p = __expf(l - red[16]);
                ps[tid] = p;
                float sum = p;
#pragma unroll
                for (int o = 16; o; o >>= 1) sum += __shfl_xor_sync(0xffffffffu, sum, o);
                if (lane == 0) red[wid] = sum;
                __syncthreads();
                if (tid < 32) {
                    float v = (tid < 16) ? red[tid] : 0.f;
#pragma unroll
                    for (int o = 8; o; o >>= 1) v += __shfl_xor_sync(0xffffffffu, v, o);
                    if (tid == 0) red[17] = v;
                }
                __syncthreads();
                inv = 1.0f / red[17];
                cur_b = b;
            }

            const int sub = tid >> 7, e4i = tid & 127;
            const int e4 = half * 128 + e4i;
            const int t0 = tc * 128 + sub * 32;
            const float4* se4 = reinterpret_cast<const float4*>(se)
                              + ((size_t)(b * T + t0)) * 256 + e4;
            float4 acc = make_float4(0.f, 0.f, 0.f, 0.f);
#pragma unroll
            for (int i = 0; i < 32; i++) {
                float pw = ps[t0 + i];
                float4 v = se4[(size_t)i * 256];
                acc.x += pw * v.x; acc.y += pw * v.y;
                acc.z += pw * v.z; acc.w += pw * v.w;
            }
            acc.x *= inv; acc.y *= inv; acc.z *= inv; acc.w *= inv;
            const int pp = tc * 4 + sub;
            reinterpret_cast<float4*>(g_ctxpart)[(size_t)(pp * B + b) * 256 + e4] = acc;
        }
    }
    grid_barrier();

    // ===== PD (tick 3): z-ctx partials, 256 tiles = kb(16 of k=64) x jt(16) ===
    if (blockIdx.x == 0 && tid == 0) g_tick[2] = 0;
    for (;;) {
        __syncthreads();
        if (tid == 0) s_tile = atomicAdd(&g_tick[3], 1u);
        __syncthreads();
        const unsigned int tile = s_tile;
        if (tile >= 256u) break;
        const int kb = tile >> 4, jt = tile & 15;
        const int j = jt * 256 + (tid & 255);
        const int bh = tid >> 8;
        const int k0 = kb * 64;

        for (int idx = tid; idx < 32 * 64; idx += NT) {
            int b = idx >> 6, kk = idx & 63;
            const float* cp = g_ctxpart + (size_t)b * E + k0 + kk;
            float s = 0.f;
#pragma unroll
            for (int pp = 0; pp < 16; pp++) s += cp[(size_t)pp * (B * E)];
            pool[kk * 36 + b] = s;
        }
        __syncthreads();

        unsigned long long acc[8];
#pragma unroll
        for (int p = 0; p < 8; p++) acc[p] = 0ull;
        const float* wcol = Wk + (size_t)(DIN + k0) * G4 + j;
#pragma unroll 8
        for (int kk = 0; kk < 64; kk++) {
            float w = wcol[(size_t)kk * G4];
            unsigned long long ww = pack2(w, w);
            const unsigned long long* xp =
                reinterpret_cast<const unsigned long long*>(&pool[kk * 36]) + bh * 8;
#pragma unroll
            for (int p = 0; p < 8; p++) acc[p] = fma2(xp[p], ww, acc[p]);
        }
        float* outp = g_zpart + (size_t)(NSPL_IND + kb) * (B * G4);
#pragma unroll
        for (int p = 0; p < 8; p++) {
            float a, b2; unpack2(acc[p], a, b2);
            outp[(size_t)(bh * 16 + 2 * p) * G4 + j] = a;
            outp[(size_t)(bh * 16 + 2 * p + 1) * G4 + j] = b2;
        }
    }
    grid_barrier();

    // ===== PE: reduce z partials + bias, gates, outputs =======================
    if (blockIdx.x == 0 && tid == 0) g_tick[3] = 0;
    {
        const int gtid = blockIdx.x * NT + tid;
        if (gtid < B * U) {
            const int b = gtid >> 10, u = gtid & (U - 1);
            float z[4];
#pragma unroll
            for (int g = 0; g < 4; g++) {
                int col = g * U + u;
                float s = bias[col];
                const float* zp = g_zpart + (size_t)b * G4 + col;
#pragma unroll
                for (int kb = 0; kb < NSPL; kb++)
                    s += zp[(size_t)kb * (B * G4)];
                z[g] = s;
            }
            float c_new = sigmoid_acc(z[1]) * c[gtid] + sigmoid_acc(z[0]) * tanhf(z[2]);
            float h_new = sigmoid_acc(z[3]) * tanhf(c_new);
            out[gtid]             = h_new;  // lstmout
            out[B * U + gtid]     = h_new;  // h state
            out[2 * B * U + gtid] = c_new;  // c state
        }
    }
}

// ---------------- launcher ------------------------------------------------------
extern "C" void kernel_launch(void* const* d_in, const int* in_sizes, int n_in,
                              void* d_out, int out_size) {
    const float* inputs      = (const float*)d_in[0];
    const float* h           = (const float*)d_in[1];
    const float* c           = (const float*)d_in[2];
    const float* speech_enc  = (const float*)d_in[3];
    const float* encodestate = (const float*)d_in[4];
    const float* Wa_w        = (const float*)d_in[5];
    const float* Wa_b        = (const float*)d_in[6];
    const float* va_w        = (const float*)d_in[7];
    const float* va_b        = (const float*)d_in[8];
    const float* kernel_w    = (const float*)d_in[9];
    const float* rec_kernel  = (const float*)d_in[10];
    const float* bias        = (const float*)d_in[11];
    float* out = (float*)d_out;

    // Size the grid so EVERY block is resident (grid barrier requirement).
    int nsm = 148, maxb = 1;
    cudaDeviceGetAttribute(&nsm, cudaDevAttrMultiProcessorCount, 0);
    cudaOccupancyMaxActiveBlocksPerMultiprocessor(&maxb, mono_cell, NT, 0);
    if (maxb < 1) maxb = 1;
    int grid = nsm * maxb;
    if (grid > 1024) grid = 1024;   // ticket loops are grid-size agnostic

    mono_cell<<<grid, NT>>>(inputs, h, c, speech_enc, encodestate,
                            Wa_w, Wa_b, va_w, va_b,
                            kernel_w, rec_kernel, bias, out);
}

// round 9
// speedup vs baseline: 1.3464x; 1.3464x over previous
#include <cuda_runtime.h>
#include <math.h>

#define B 32
#define T 512
#define U 1024
#define E 1024
#define DIN 256
#define G4 4096        // 4*U
#define NSPL_IND 10    // independent z chunks (2 inputs + 8 h), k=128 each
#define NSPL_CTX 16    // context z chunks, k=64 each
#define NSPL (NSPL_IND + NSPL_CTX)
#define GRID 296       // 148 SMs x 2 resident blocks
#define NT 512

// ---------------- scratch (device globals: no allocations allowed) ----------
__device__ float g_qpart[16 * B * U];
__device__ float g_query[B * U];
__device__ float g_logits[B * T];
__device__ float g_attn[B * T];
__device__ float g_ctxpart[16 * B * E];
__device__ float g_zpart[NSPL * B * G4];
__device__ unsigned int g_count = 0;  // self-resets every barrier
__device__ unsigned int g_gen = 0;    // monotonic across launches/replays

// ---------------- helpers ----------------------------------------------------
__device__ __forceinline__ unsigned long long pack2(float a, float b) {
    unsigned long long r;
    asm("mov.b64 %0, {%1, %2};" : "=l"(r) : "r"(__float_as_uint(a)), "r"(__float_as_uint(b)));
    return r;
}
__device__ __forceinline__ void unpack2(unsigned long long v, float& a, float& b) {
    unsigned int lo, hi;
    asm("mov.b64 {%0, %1}, %2;" : "=r"(lo), "=r"(hi) : "l"(v));
    a = __uint_as_float(lo); b = __uint_as_float(hi);
}
__device__ __forceinline__ unsigned long long fma2(unsigned long long x,
                                                   unsigned long long y,
                                                   unsigned long long a) {
    unsigned long long d;
    asm("fma.rn.f32x2 %0, %1, %2, %3;" : "=l"(d) : "l"(x), "l"(y), "l"(a));
    return d;
}
__device__ __forceinline__ float tanh_hw(float x) {
    float y;
    asm("tanh.approx.f32 %0, %1;" : "=f"(y) : "f"(x));
    return y;
}
__device__ __forceinline__ float sigmoid_acc(float x) {
    return 1.0f / (1.0f + expf(-x));
}
__device__ __forceinline__ float4 ldcs4(const float4* p) {
    float4 v;
    asm("ld.global.cs.v4.f32 {%0,%1,%2,%3}, [%4];"
        : "=f"(v.x), "=f"(v.y), "=f"(v.z), "=f"(v.w) : "l"(p));
    return v;
}

// Grid-wide barrier: counter + monotonic generation (replay-safe).
__device__ __forceinline__ void grid_barrier() {
    __syncthreads();
    if (threadIdx.x == 0) {
        __threadfence();
        unsigned int gen = atomicAdd(&g_gen, 0u);
        unsigned int arrived = atomicAdd(&g_count, 1u) + 1u;
        if (arrived == GRID) {
            g_count = 0;
            __threadfence();
            atomicAdd(&g_gen, 1u);
        } else {
            while (atomicAdd(&g_gen, 0u) == gen) { __nanosleep(64); }
        }
        __threadfence();
    }
    __syncthreads();
}

// ---------------- the whole cell: 7 phases, 6 barriers, static tiles ----------
__global__ void __launch_bounds__(NT, 2) mono_cell(
    const float* __restrict__ inputs, const float* __restrict__ h,
    const float* __restrict__ c, const float* __restrict__ se,
    const float* __restrict__ es, const float* __restrict__ Wa,
    const float* __restrict__ Wa_b, const float* __restrict__ va_w,
    const float* __restrict__ va_b, const float* __restrict__ Wk,
    const float* __restrict__ Wr, const float* __restrict__ bias,
    float* __restrict__ out)
{
    __shared__ __align__(16) float pool[128 * 36];   // 18.4KB, reused per phase
    const int tid = threadIdx.x;
    const int bx = blockIdx.x;
    const int gtid = bx * NT + tid;

    // ===== P1: query partials (64 blk) + independent z partials (160 blk) =====
    if (bx < 64) {
        const int tile = bx >> 4, kb = bx & 15;
        const int k0 = kb * 64;
        const int u = tile * 256 + (tid & 255);
        const int bh = tid >> 8;

        for (int idx = tid; idx < 32 * 64; idx += NT) {
            int b = idx >> 6, k = idx & 63;
            pool[k * 36 + b] = h[b * U + k0 + k];
        }
        __syncthreads();

        unsigned long long acc[8];
#pragma unroll
        for (int p = 0; p < 8; p++) acc[p] = 0ull;
        const float* wcol = Wa + (size_t)k0 * U + u;
#pragma unroll 8
        for (int k = 0; k < 64; k++) {
            float w = wcol[(size_t)k * U];
            unsigned long long ww = pack2(w, w);
            const unsigned long long* xp =
                reinterpret_cast<const unsigned long long*>(&pool[k * 36]) + bh * 8;
#pragma unroll
            for (int p = 0; p < 8; p++) acc[p] = fma2(xp[p], ww, acc[p]);
        }
        float* outp = g_qpart + (size_t)kb * (B * U);
#pragma unroll
        for (int p = 0; p < 8; p++) {
            float a, b2; unpack2(acc[p], a, b2);
            outp[(bh * 16 + 2 * p) * U + u] = a;
            outp[(bh * 16 + 2 * p + 1) * U + u] = b2;
        }
    } else if (bx < 64 + 160) {
        const int zi = bx - 64;
        const int kb = zi >> 4, jt = zi & 15;
        const int j = jt * 256 + (tid & 255);
        const int bh = tid >> 8;

        const float* xsrc; int x_ld, xk0;
        const float* W;    int wk0;
        if (kb < 2) { xsrc = inputs; x_ld = DIN; xk0 = kb * 128;       W = Wk; wk0 = kb * 128; }
        else        { xsrc = h;      x_ld = U;   xk0 = (kb - 2) * 128; W = Wr; wk0 = (kb - 2) * 128; }

        for (int idx = tid; idx < 32 * 128; idx += NT) {
            int b = idx >> 7, kk = idx & 127;
            pool[kk * 36 + b] = xsrc[(size_t)b * x_ld + xk0 + kk];
        }
        __syncthreads();

        unsigned long long acc[8];
#pragma unroll
        for (int p = 0; p < 8; p++) acc[p] = 0ull;
        const float* wcol = W + (size_t)wk0 * G4 + j;
#pragma unroll 8
        for (int kk = 0; kk < 128; kk++) {
            float w = wcol[(size_t)kk * G4];
            unsigned long long ww = pack2(w, w);
            const unsigned long long* xp =
                reinterpret_cast<const unsigned long long*>(&pool[kk * 36]) + bh * 8;
#pragma unroll
            for (int p = 0; p < 8; p++) acc[p] = fma2(xp[p], ww, acc[p]);
        }
        float* outp = g_zpart + (size_t)kb * (B * G4);
#pragma unroll
        for (int p = 0; p < 8; p++) {
            float a, b2; unpack2(acc[p], a, b2);
            outp[(size_t)(bh * 16 + 2 * p) * G4 + j] = a;
            outp[(size_t)(bh * 16 + 2 * p + 1) * G4 + j] = b2;
        }
    }
    grid_barrier();

    // ===== P1b: reduce query partials + bias (all blocks, cheap) ==============
    if (gtid < B * U) {
        float s = Wa_b[gtid & (U - 1)];
#pragma unroll
        for (int kb = 0; kb < 16; kb++) s += g_qpart[kb * (B * U) + gtid];
        g_query[gtid] = s;
    }
    grid_barrier();

    // ===== P2: scores with smem-cached q[b] and va =============================
    // 288 blocks: 9 per batch; each handles up to 57 rows, warp-per-row.
    if (bx < 288) {
        const int b = bx / 9;
        const int sl = bx - b * 9;

        // pool: q[0..1023], va[1024..2047] — q is ALREADY reduced (g_query)
        for (int i4 = tid; i4 < 256; i4 += NT) {
            reinterpret_cast<float4*>(pool)[i4] =
                reinterpret_cast<const float4*>(g_query + b * U)[i4];
            reinterpret_cast<float4*>(pool + 1024)[i4] =
                reinterpret_cast<const float4*>(va_w)[i4];
        }
        __syncthreads();

        const float vb = va_b[0];
        const int lane = tid & 31;
        const int r0 = sl * 57;
        const int r1 = (r0 + 57 < T) ? (r0 + 57) : T;
        const float4* qs = reinterpret_cast<const float4*>(pool);
        const float4* vs = reinterpret_cast<const float4*>(pool + 1024);

        for (int r = r0 + (tid >> 5); r < r1; r += 16) {
            const float4* erow = reinterpret_cast<const float4*>(es)
                               + (size_t)(b * T + r) * 256;
            float4 e[8];
#pragma unroll
            for (int i = 0; i < 8; i++) e[i] = ldcs4(&erow[lane + i * 32]);
            float s = 0.f;
#pragma unroll
            for (int i = 0; i < 8; i++) {
                int u4 = lane + i * 32;
                float4 q4 = qs[u4];
                float4 v4 = vs[u4];
                s += tanh_hw(q4.x + e[i].x) * v4.x;
                s += tanh_hw(q4.y + e[i].y) * v4.y;
                s += tanh_hw(q4.z + e[i].z) * v4.z;
                s += tanh_hw(q4.w + e[i].w) * v4.w;
            }
#pragma unroll
            for (int o = 16; o; o >>= 1) s += __shfl_xor_sync(0xffffffffu, s, o);
            if (lane == 0) g_logits[b * T + r] = s + vb;
        }
    }
    grid_barrier();

    // ===== P3: softmax over T per batch (32 blocks, tiny) =====================
    if (bx < 32) {
        float* red = pool;
        const int b = bx;
        const int lane = tid & 31, wid = tid >> 5;

        float l = g_logits[b * T + tid];
        float m = l;
#pragma unroll
        for (int o = 16; o; o >>= 1) m = fmaxf(m, __shfl_xor_sync(0xffffffffu, m, o));
        if (lane == 0) red[wid] = m;
        __syncthreads();
        if (tid < 32) {
            float v = red[tid & 15];
#pragma unroll
            for (int o = 8; o; o >>= 1) v = fmaxf(v, __shfl_xor_sync(0xffffffffu, v, o));
            if (tid == 0) red[16] = v;
        }
        __syncthreads();
        float p = __expf(l - red[16]);
        float sum = p;
#pragma unroll
        for (int o = 16; o; o >>= 1) sum += __shfl_xor_sync(0xffffffffu, sum, o);
        if (lane == 0) red[wid] = sum;
        __syncthreads();
        if (tid < 32) {
            float v = (tid < 16) ? red[tid] : 0.f;
#pragma unroll
            for (int o = 8; o; o >>= 1) v += __shfl_xor_sync(0xffffffffu, v, o);
            if (tid == 0) red[17] = v;
        }
        __syncthreads();
        g_attn[b * T + tid] = p / red[17];
    }
    grid_barrier();

    // ===== P4: context partials (256 blocks, smem-staged attn) ================
    if (bx < 256) {
        const int b = bx >> 3, half = (bx >> 2) & 1, tc = bx & 3;
        if (tid < 128) pool[tid] = g_attn[b * T + tc * 128 + tid];
        __syncthreads();

        const int sub = tid >> 7, e4i = tid & 127;
        const int e4 = half * 128 + e4i;
        const int t0 = tc * 128 + sub * 32;

        const float* ap = pool + sub * 32;
        const float4* se4 = reinterpret_cast<const float4*>(se)
                          + ((size_t)(b * T + t0)) * 256 + e4;
        float4 acc = make_float4(0.f, 0.f, 0.f, 0.f);
#pragma unroll
        for (int i = 0; i < 32; i++) {
            float p = ap[i];
            float4 v = ldcs4(&se4[(size_t)i * 256]);
            acc.x += p * v.x; acc.y += p * v.y; acc.z += p * v.z; acc.w += p * v.w;
        }
        const int pp = tc * 4 + sub;
        reinterpret_cast<float4*>(g_ctxpart)[(size_t)(pp * B + b) * 256 + e4] = acc;
    }
    grid_barrier();

    // ===== P6: z-ctx partials; staging sums the 16 ctx partials inline ========
    // 256 blocks: 16 k-chunks of 64 x 16 j-tiles of 256.
    if (bx < 256) {
        const int kb = bx >> 4, jt = bx & 15;
        const int j = jt * 256 + (tid & 255);
        const int bh = tid >> 8;
        const int k0 = kb * 64;

        for (int idx = tid; idx < 32 * 64; idx += NT) {
            int b = idx >> 6, kk = idx & 63;
            const float* cp = g_ctxpart + (size_t)b * E + k0 + kk;
            float s = 0.f;
#pragma unroll
            for (int pp = 0; pp < 16; pp++) s += cp[(size_t)pp * (B * E)];
            pool[kk * 36 + b] = s;
        }
        __syncthreads();

        unsigned long long acc[8];
#pragma unroll
        for (int p = 0; p < 8; p++) acc[p] = 0ull;
        const float* wcol = Wk + (size_t)(DIN + k0) * G4 + j;
#pragma unroll 8
        for (int kk = 0; kk < 64; kk++) {
            float w = wcol[(size_t)kk * G4];
            unsigned long long ww = pack2(w, w);
            const unsigned long long* xp =
                reinterpret_cast<const unsigned long long*>(&pool[kk * 36]) + bh * 8;
#pragma unroll
            for (int p = 0; p < 8; p++) acc[p] = fma2(xp[p], ww, acc[p]);
        }
        float* outp = g_zpart + (size_t)(NSPL_IND + kb) * (B * G4);
#pragma unroll
        for (int p = 0; p < 8; p++) {
            float a, b2; unpack2(acc[p], a, b2);
            outp[(size_t)(bh * 16 + 2 * p) * G4 + j] = a;
            outp[(size_t)(bh * 16 + 2 * p + 1) * G4 + j] = b2;
        }
    }
    grid_barrier();

    // ===== P7: reduce z partials + bias, gates, outputs =======================
    if (gtid < B * U) {
        const int b = gtid >> 10, u = gtid & (U - 1);
        float z[4];
#pragma unroll
        for (int g = 0; g < 4; g++) {
            int col = g * U + u;
            float s = bias[col];
            const float* zp = g_zpart + (size_t)b * G4 + col;
#pragma unroll
            for (int kb = 0; kb < NSPL; kb++)
                s += zp[(size_t)kb * (B * G4)];
            z[g] = s;
        }
        float c_new = sigmoid_acc(z[1]) * c[gtid] + sigmoid_acc(z[0]) * tanhf(z[2]);
        float h_new = sigmoid_acc(z[3]) * tanhf(c_new);
        out[gtid]             = h_new;  // lstmout
        out[B * U + gtid]     = h_new;  // h state
        out[2 * B * U + gtid] = c_new;  // c state
    }
}

// ---------------- launcher ------------------------------------------------------
extern "C" void kernel_launch(void* const* d_in, const int* in_sizes, int n_in,
                              void* d_out, int out_size) {
    const float* inputs      = (const float*)d_in[0];
    const float* h           = (const float*)d_in[1];
    const float* c           = (const float*)d_in[2];
    const float* speech_enc  = (const float*)d_in[3];
    const float* encodestate = (const float*)d_in[4];
    const float* Wa_w        = (const float*)d_in[5];
    const float* Wa_b        = (const float*)d_in[6];
    const float* va_w        = (const float*)d_in[7];
    const float* va_b        = (const float*)d_in[8];
    const float* kernel_w    = (const float*)d_in[9];
    const float* rec_kernel  = (const float*)d_in[10];
    const float* bias        = (const float*)d_in[11];
    float* out = (float*)d_out;

    mono_cell<<<GRID, NT>>>(inputs, h, c, speech_enc, encodestate,
                            Wa_w, Wa_b, va_w, va_b,
                            kernel_w, rec_kernel, bias, out);
}